// round 1
// baseline (speedup 1.0000x reference)
#include <cuda_runtime.h>
#include <cuda_bf16.h>

// Problem constants (shapes are fixed by the dataset; sizes still read from in_sizes)
#define MAXN 50176
#define MAXE 850176

// -------- scratch (device globals; no allocation allowed) --------
__device__ float  g_xl[MAXN * 64];      // lin(x)  [N,64]
__device__ float  g_si[MAXN];           // per-node dst-side logit
__device__ float  g_sj[MAXN];           // per-node src-side logit
__device__ int    g_deg[MAXN];          // in-degree (incl. self loop)
__device__ int    g_rowptr[MAXN + 1];
__device__ int    g_cursor[MAXN];
__device__ int    g_csrc[MAXE + MAXN];  // CSR src ids (dst-sorted)
__device__ double g_bnsum[128];         // [0:64) sum, [64:128) sumsq
__device__ float  g_scale[64];
__device__ float  g_shift[64];

// -------- K0: init --------
__global__ void k_init(int N) {
    int i = blockIdx.x * blockDim.x + threadIdx.x;
    if (i < N) g_deg[i] = 1;            // self loop pre-counted
    if (i < 128) g_bnsum[i] = 0.0;
}

// -------- K1: xl = x @ W^T, plus per-node attention scalars --------
__global__ void k_gemm(const float* __restrict__ x, const float* __restrict__ W,
                       const float* __restrict__ emb,
                       const float* __restrict__ att_i, const float* __restrict__ att_j,
                       const float* __restrict__ att_em_i, const float* __restrict__ att_em_j,
                       int N) {
    __shared__ float2 Wt2[64][32];      // Wt2[k][l] = (W[2l][k], W[2l+1][k])
    int tid = threadIdx.x;
    for (int s = tid; s < 64 * 32; s += 256) {
        int k = s >> 5, l = s & 31;
        Wt2[k][l] = make_float2(W[(2 * l) * 64 + k], W[(2 * l + 1) * 64 + k]);
    }
    __syncthreads();
    int warp = tid >> 5, lane = tid & 31;
    int c0 = 2 * lane;
    float ai0 = att_i[c0],    ai1 = att_i[c0 + 1];
    float aj0 = att_j[c0],    aj1 = att_j[c0 + 1];
    float e0i = att_em_i[c0], e1i = att_em_i[c0 + 1];
    float e0j = att_em_j[c0], e1j = att_em_j[c0 + 1];

    for (int r = blockIdx.x * 8 + warp; r < N; r += gridDim.x * 8) {
        float xv0 = x[r * 64 + lane];
        float xv1 = x[r * 64 + 32 + lane];
        float a0 = 0.f, a1 = 0.f;
#pragma unroll
        for (int k = 0; k < 32; k++) {
            float xk = __shfl_sync(0xffffffffu, xv0, k);
            float2 w = Wt2[k][lane];
            a0 = fmaf(xk, w.x, a0);
            a1 = fmaf(xk, w.y, a1);
        }
#pragma unroll
        for (int k = 0; k < 32; k++) {
            float xk = __shfl_sync(0xffffffffu, xv1, k);
            float2 w = Wt2[32 + k][lane];
            a0 = fmaf(xk, w.x, a0);
            a1 = fmaf(xk, w.y, a1);
        }
        float2 o2 = make_float2(a0, a1);
        *(float2*)&g_xl[r * 64 + c0] = o2;

        float2 em = *(const float2*)&emb[r * 64 + c0];
        float si = a0 * ai0 + a1 * ai1 + em.x * e0i + em.y * e1i;
        float sj = a0 * aj0 + a1 * aj1 + em.x * e0j + em.y * e1j;
#pragma unroll
        for (int o = 16; o; o >>= 1) {
            si += __shfl_xor_sync(0xffffffffu, si, o);
            sj += __shfl_xor_sync(0xffffffffu, sj, o);
        }
        if (lane == 0) { g_si[r] = si; g_sj[r] = sj; }
    }
}

// -------- K2: in-degree count --------
__global__ void k_count(const int* __restrict__ ei, int E) {
    int e = blockIdx.x * blockDim.x + threadIdx.x;
    if (e < E) atomicAdd(&g_deg[ei[E + e]], 1);
}

// -------- K3: exclusive scan (single block, warp-scan tiles) --------
__global__ void k_scan(int N) {
    __shared__ int wsum[32];
    __shared__ int s_off, s_tile;
    int tid = threadIdx.x, lane = tid & 31, wid = tid >> 5;
    if (tid == 0) s_off = 0;
    __syncthreads();
    for (int base = 0; base < N; base += 1024) {
        int i = base + tid;
        int v = (i < N) ? g_deg[i] : 0;
        int incl = v;
#pragma unroll
        for (int d = 1; d < 32; d <<= 1) {
            int t = __shfl_up_sync(0xffffffffu, incl, d);
            if (lane >= d) incl += t;
        }
        if (lane == 31) wsum[wid] = incl;
        __syncthreads();
        if (wid == 0) {
            int s = wsum[lane];
            int sincl = s;
#pragma unroll
            for (int d = 1; d < 32; d <<= 1) {
                int t = __shfl_up_sync(0xffffffffu, sincl, d);
                if (lane >= d) sincl += t;
            }
            wsum[lane] = sincl - s;       // exclusive warp offsets
            if (lane == 31) s_tile = sincl;
        }
        __syncthreads();
        int excl = s_off + wsum[wid] + incl - v;
        if (i < N) { g_rowptr[i] = excl; g_cursor[i] = excl; }
        __syncthreads();
        if (tid == 0) s_off += s_tile;
    }
    __syncthreads();
    if (tid == 0) g_rowptr[N] = s_off;
}

// -------- K4: scatter edges (+ self loops) into CSR --------
__global__ void k_scatter(const int* __restrict__ ei, int E, int N) {
    int idx = blockIdx.x * blockDim.x + threadIdx.x;
    if (idx < E) {
        int s = ei[idx], d = ei[E + idx];
        int p = atomicAdd(&g_cursor[d], 1);
        g_csrc[p] = s;
    } else if (idx < E + N) {
        int n = idx - E;
        int p = atomicAdd(&g_cursor[n], 1);
        g_csrc[p] = n;
    }
}

// -------- K5: per-node softmax + weighted gather (one warp / node) --------
__global__ void k_agg(const float* __restrict__ bias, float* __restrict__ out, int N) {
    int gwarp = (blockIdx.x * blockDim.x + threadIdx.x) >> 5;
    int lane = threadIdx.x & 31;
    if (gwarp >= N) return;
    int i = gwarp;
    int beg = g_rowptr[i], end = g_rowptr[i + 1];
    float si = g_si[i];

    // pass 1: max (lane-strided)
    float m = -1e30f;
    for (int k = beg + lane; k < end; k += 32) {
        float a = si + g_sj[g_csrc[k]];
        a = a >= 0.f ? a : 0.2f * a;
        m = fmaxf(m, a);
    }
#pragma unroll
    for (int o = 16; o; o >>= 1) m = fmaxf(m, __shfl_xor_sync(0xffffffffu, m, o));

    // pass 2: exp-weighted gather (edge-serial, channel-parallel)
    int c0 = 2 * lane;
    float ax = 0.f, ay = 0.f, ssum = 0.f;
    for (int k = beg; k < end; ++k) {
        int s = g_csrc[k];                      // warp-uniform broadcast load
        float a = si + g_sj[s];
        a = a >= 0.f ? a : 0.2f * a;
        float w = __expf(a - m);
        ssum += w;
        float2 v = *(const float2*)&g_xl[s * 64 + c0];
        ax = fmaf(w, v.x, ax);
        ay = fmaf(w, v.y, ay);
    }
    float inv = 1.f / (ssum + 1e-16f);
    float2 b2 = *(const float2*)&bias[c0];
    float2 o2 = make_float2(ax * inv + b2.x, ay * inv + b2.y);
    *(float2*)&out[i * 64 + c0] = o2;
}

// -------- K6: BN stats (double partials) --------
__global__ void k_bnred(const float* __restrict__ out, int N) {
    __shared__ double ssum[256], ssq[256];
    int tid = threadIdx.x;
    double s = 0.0, q = 0.0;
    int total = N * 64;
    for (int idx = blockIdx.x * 256 + tid; idx < total; idx += gridDim.x * 256) {
        double v = (double)out[idx];            // idx % 64 == tid % 64 (strides % 64 == 0)
        s += v; q += v * v;
    }
    ssum[tid] = s; ssq[tid] = q;
    __syncthreads();
    if (tid < 128) { ssum[tid] += ssum[tid + 128]; ssq[tid] += ssq[tid + 128]; }
    __syncthreads();
    if (tid < 64) {
        double S = ssum[tid] + ssum[tid + 64];
        double Q = ssq[tid] + ssq[tid + 64];
        atomicAdd(&g_bnsum[tid], S);
        atomicAdd(&g_bnsum[64 + tid], Q);
    }
}

// -------- K6b: finalize BN scale/shift --------
__global__ void k_bnfinal(const float* __restrict__ gamma, const float* __restrict__ beta, int N) {
    int c = threadIdx.x;
    if (c < 64) {
        double mu  = g_bnsum[c] / (double)N;
        double var = g_bnsum[64 + c] / (double)N - mu * mu;
        float sc = (float)(rsqrt(var + 1e-5)) * gamma[c];
        g_scale[c] = sc;
        g_shift[c] = beta[c] - (float)mu * sc;
    }
}

// -------- K7: apply BN + ReLU --------
__global__ void k_bnapply(float* __restrict__ out, int N) {
    int idx = blockIdx.x * blockDim.x + threadIdx.x;
    if (idx >= N * 64) return;
    int c = idx & 63;
    float v = fmaf(out[idx], g_scale[c], g_shift[c]);
    out[idx] = fmaxf(v, 0.f);
}

extern "C" void kernel_launch(void* const* d_in, const int* in_sizes, int n_in,
                              void* d_out, int out_size) {
    const float* x        = (const float*)d_in[0];
    const int*   ei       = (const int*)d_in[1];
    const float* emb      = (const float*)d_in[2];
    const float* W        = (const float*)d_in[3];
    const float* att_i    = (const float*)d_in[4];
    const float* att_j    = (const float*)d_in[5];
    const float* att_em_i = (const float*)d_in[6];
    const float* att_em_j = (const float*)d_in[7];
    const float* bias     = (const float*)d_in[8];
    const float* gamma    = (const float*)d_in[9];
    const float* beta     = (const float*)d_in[10];
    float* out = (float*)d_out;

    int N = in_sizes[0] / 64;
    int E = in_sizes[1] / 2;

    k_init<<<(N + 255) / 256, 256>>>(N);
    k_gemm<<<1480, 256>>>(x, W, emb, att_i, att_j, att_em_i, att_em_j, N);
    k_count<<<(E + 255) / 256, 256>>>(ei, E);
    k_scan<<<1, 1024>>>(N);
    k_scatter<<<(E + N + 255) / 256, 256>>>(ei, E, N);
    k_agg<<<(N + 7) / 8, 256>>>(bias, out, N);
    k_bnred<<<1184, 256>>>(out, N);
    k_bnfinal<<<1, 64>>>(gamma, beta, N);
    k_bnapply<<<(N * 64 + 255) / 256, 256>>>(out, N);
}